// round 7
// baseline (speedup 1.0000x reference)
#include <cuda_runtime.h>
#include <cstdint>
#include <math.h>

#define BB 128
#define NN 1000
#define DD 196
#define KK 48
#define NC 64            // candidate columns (top-NC of x per batch row)
#define NO (DD - NC)     // 132 other columns
#define NWARPS 32
#define THREADS (NWARPS * 32)
#define BATCH 8          // samples buffered per warp
#define RECW 100         // words per sample record: 4 team-slots * 24 + moK at +96

// dynamic smem layout (bytes)
#define OFF_ACC   0
#define SZ_ACC    (KK * DD * 4)                   // 37632
#define OFF_RECS  (OFF_ACC + SZ_ACC)              // 37632 (16B aligned)
#define SZ_RECS   (NWARPS * BATCH * RECW * 4)     // 102400
#define OFF_CIDX  (OFF_RECS + SZ_RECS)            // 140032
#define OFF_OIDX  (OFF_CIDX + NC * 2)             // 140160
#define OFF_FLAGC (OFF_OIDX + NO * 2)             // 140424
#define OFF_FLAGN (OFF_FLAGC + 4)                 // 140428
#define SMEM_TOTAL (OFF_FLAGN + NN * 2 + 16)      // ~142.4 KB

__device__ __forceinline__ unsigned f2key(float v) {
    unsigned u = __float_as_uint(v);
    return u ^ ((unsigned)((int)u >> 31) | 0x80000000u);
}

// Exact full-width fallback: top-KK of all 196 perturbed values, d-ascending ranks.
__device__ __noinline__ void fallback_select(const float* __restrict__ row,
                                             const float* __restrict__ xb,
                                             float sigma, int* acc,
                                             int lane, unsigned lt)
{
    const unsigned FULL = 0xffffffffu;
    unsigned key[7];
#pragma unroll
    for (int j = 0; j < 7; ++j) {
        int d = j * 32 + lane;
        key[j] = (d < DD) ? f2key(fmaf(sigma, row[d], xb[d])) : 0u;
    }
    unsigned prefix = 0;
    for (int bit = 31; bit >= 0; --bit) {
        unsigned t = prefix | (1u << bit);
        int c = 0;
#pragma unroll
        for (int j = 0; j < 7; ++j) c += (key[j] >= t);
        c = __reduce_add_sync(FULL, c);
        if (c >= KK) { prefix = t; if (c == KK) break; }
    }
    int cgt = 0;
#pragma unroll
    for (int j = 0; j < 7; ++j) cgt += (key[j] > prefix);
    cgt = __reduce_add_sync(FULL, cgt);
    int rem = KK - cgt;
    int selb = 0, eqb = 0;
#pragma unroll
    for (int j = 0; j < 7; ++j) {
        bool gt = key[j] > prefix;
        bool eq = (key[j] == prefix);
        unsigned be = __ballot_sync(FULL, eq);
        bool sel = gt || (eq && (eqb + __popc(be & lt)) < rem);
        unsigned bs = __ballot_sync(FULL, sel);
        if (sel) atomicAdd(&acc[(selb + __popc(bs & lt)) * DD + (j * 32 + lane)], 1);
        eqb += __popc(be);
        selb += __popc(bs);
    }
}

__global__ __launch_bounds__(THREADS, 1)
void ptk_kernel(const float* __restrict__ x,
                const float* __restrict__ noise,
                const float* __restrict__ sigma_p,
                float* __restrict__ out)
{
    extern __shared__ char smem_raw[];
    int*      acc     = (int*)(smem_raw + OFF_ACC);
    unsigned* recs    = (unsigned*)(smem_raw + OFF_RECS);
    short*    cidx    = (short*)(smem_raw + OFF_CIDX);
    short*    oidx    = (short*)(smem_raw + OFF_OIDX);
    int*      flagCnt = (int*)(smem_raw + OFF_FLAGC);
    short*    flagN   = (short*)(smem_raw + OFF_FLAGN);

    const int b = blockIdx.x, tid = threadIdx.x, lane = tid & 31, warp = tid >> 5;
    const unsigned lt = (1u << lane) - 1u;
    const unsigned FULL = 0xffffffffu;

    for (int i = tid; i < KK * DD; i += THREADS) acc[i] = 0;
    if (tid == 0) *flagCnt = 0;

    // ---- per-b precompute (warp 0): exact top-NC columns of x ----
    if (warp == 0) {
        unsigned key[7];
#pragma unroll
        for (int j = 0; j < 7; ++j) {
            int d = j * 32 + lane;
            key[j] = (d < DD) ? f2key(x[b * DD + d]) : 0u;
        }
        unsigned prefix = 0;
        for (int bit = 31; bit >= 0; --bit) {
            unsigned t = prefix | (1u << bit);
            int c = 0;
#pragma unroll
            for (int j = 0; j < 7; ++j) c += (key[j] >= t);
            c = __reduce_add_sync(FULL, c);
            if (c >= NC) { prefix = t; if (c == NC) break; }
        }
        int cgt = 0;
#pragma unroll
        for (int j = 0; j < 7; ++j) cgt += (key[j] > prefix);
        cgt = __reduce_add_sync(FULL, cgt);
        int rem = NC - cgt;
        int cb = 0, ob = 0, eqb = 0;
#pragma unroll
        for (int j = 0; j < 7; ++j) {
            int d = j * 32 + lane;
            bool valid = d < DD;
            bool gt = key[j] > prefix;
            bool eq = valid && (key[j] == prefix);
            unsigned be = __ballot_sync(FULL, eq);
            bool sel = gt || (eq && (eqb + __popc(be & lt)) < rem);
            unsigned bs = __ballot_sync(FULL, sel);
            unsigned bo = __ballot_sync(FULL, valid && !sel);
            if (sel)        cidx[cb + __popc(bs & lt)] = (short)d;
            else if (valid) oidx[ob + __popc(bo & lt)] = (short)d;
            eqb += __popc(be); cb += __popc(bs); ob += __popc(bo);
        }
    }
    __syncthreads();

    const float sigma = sigma_p ? *sigma_p : 0.05f;
    const float* xb = x + b * DD;

    // per-lane static gather indices + x values
    const int dC0 = cidx[lane];
    const int dC1 = cidx[32 + lane];
    const float xC0 = xb[dC0];
    const float xC1 = xb[dC1];
    int dO[5]; float xO[5];
#pragma unroll
    for (int j = 0; j < 5; ++j) {
        int p = j * 32 + lane;
        if (p < NO) { dO[j] = oidx[p]; xO[j] = xb[dO[j]]; }
        else        { dO[j] = 0;       xO[j] = -INFINITY; }
    }

    const float* nbase = noise + (size_t)b * NN * DD;
    unsigned* myrecs = recs + warp * BATCH * RECW;

    // phase-1 write slots for this lane's two candidates
    const int w0 = (lane >> 4) * 24 + (lane & 15);         // candidate lane
    const int w1 = (2 + (lane >> 4)) * 24 + (lane & 15);   // candidate 32+lane

    const int wstart = (NN * warp) / NWARPS;
    const int wend   = (NN * (warp + 1)) / NWARPS;

    const int s    = lane >> 2;        // team sample index (phase 2)
    const int h    = lane & 3;         // team slot
    const unsigned tmask = 0xFu << (lane & ~3);

    for (int base = wstart; base < wend; base += BATCH) {
        const int m = min(BATCH, wend - base);

        // ---- phase 1 (warp-coop): gather keys for m rows, groups of 4 for MLP ----
        for (int g = 0; g < m; g += 4) {
            const int gm = min(4, m - g);
            float c0[4], c1[4], o0[4], o1[4], o2[4], o3[4], o4[4];
#pragma unroll
            for (int t = 0; t < 4; ++t) {
                const float* row = nbase + (size_t)(base + g + ((t < gm) ? t : 0)) * DD;
                c0[t] = row[dC0]; c1[t] = row[dC1];
                o0[t] = row[dO[0]]; o1[t] = row[dO[1]]; o2[t] = row[dO[2]];
                o3[t] = row[dO[3]]; o4[t] = row[dO[4]];
            }
#pragma unroll
            for (int t = 0; t < 4; ++t) {
                if (t >= gm) break;
                float mo = fmaf(sigma, o0[t], xO[0]);
                mo = fmaxf(mo, fmaf(sigma, o1[t], xO[1]));
                mo = fmaxf(mo, fmaf(sigma, o2[t], xO[2]));
                mo = fmaxf(mo, fmaf(sigma, o3[t], xO[3]));
                mo = fmaxf(mo, fmaf(sigma, o4[t], xO[4]));
                unsigned k0 = f2key(fmaf(sigma, c0[t], xC0));
                unsigned k1 = f2key(fmaf(sigma, c1[t], xC1));
                unsigned moK = __reduce_max_sync(FULL, f2key(mo));
                unsigned* rec = myrecs + (g + t) * RECW;
                rec[w0] = k0;
                rec[w1] = k1;
                if (lane == 0) rec[96] = moK;
            }
        }
        __syncwarp();

        // ---- phase 2: team-of-4 per sample, 16 keys/lane in registers ----
        if (s < m) {
            unsigned k[16];
            const uint4* rp = (const uint4*)(myrecs + s * RECW + h * 24);
#pragma unroll
            for (int i = 0; i < 4; ++i) {
                uint4 v = rp[i];
                k[4 * i] = v.x; k[4 * i + 1] = v.y; k[4 * i + 2] = v.z; k[4 * i + 3] = v.w;
            }
            unsigned moK = myrecs[s * RECW + 96];

            unsigned kmin = k[0], kmax = k[0];
#pragma unroll
            for (int j = 1; j < 16; ++j) { kmin = min(kmin, k[j]); kmax = max(kmax, k[j]); }
            kmin = min(kmin, __shfl_xor_sync(tmask, kmin, 1));
            kmin = min(kmin, __shfl_xor_sync(tmask, kmin, 2));
            kmax = max(kmax, __shfl_xor_sync(tmask, kmax, 1));
            kmax = max(kmax, __shfl_xor_sync(tmask, kmax, 2));

            unsigned vT;
            if (kmin == kmax) {
                vT = kmin;
            } else {
                int hb = 31 - __clz(kmin ^ kmax);
                unsigned prefix = (hb >= 31) ? 0u : (kmin & ~((1u << (hb + 1)) - 1u));
                for (int bit = hb; bit >= 0; --bit) {
                    unsigned t = prefix | (1u << bit);
                    int c = 0;
#pragma unroll
                    for (int j = 0; j < 16; ++j) c += (k[j] >= t);
                    c += __shfl_xor_sync(tmask, c, 1);
                    c += __shfl_xor_sync(tmask, c, 2);
                    if (c >= KK) { prefix = t; if (c == KK) break; }
                }
                vT = prefix;
            }

            if (moK >= vT) {
                if (h == 0) {
                    int idx = atomicAdd(flagCnt, 1);
                    if (idx < NN) flagN[idx] = (short)(base + s);
                }
            } else {
                int cgt = 0, ceq = 0;
#pragma unroll
                for (int j = 0; j < 16; ++j) { cgt += (k[j] > vT); ceq += (k[j] == vT); }
                unsigned pack = (unsigned)cgt | ((unsigned)ceq << 8);
                int tb = lane & ~3;
                unsigned p0 = __shfl_sync(tmask, pack, tb + 0);
                unsigned p1 = __shfl_sync(tmask, pack, tb + 1);
                unsigned p2 = __shfl_sync(tmask, pack, tb + 2);
                unsigned p3 = __shfl_sync(tmask, pack, tb + 3);
                int garr[4] = { (int)(p0 & 255), (int)(p1 & 255), (int)(p2 & 255), (int)(p3 & 255) };
                int earr[4] = { (int)(p0 >> 8), (int)(p1 >> 8), (int)(p2 >> 8), (int)(p3 >> 8) };
                int rem = KK - (garr[0] + garr[1] + garr[2] + garr[3]);

                int eqb = 0, selb = 0;
#pragma unroll
                for (int h2 = 0; h2 < 3; ++h2) {
                    if (h2 < h) {
                        int take = rem - eqb;
                        take = take < 0 ? 0 : (take > earr[h2] ? earr[h2] : take);
                        selb += garr[h2] + take;
                        eqb  += earr[h2];
                    }
                }

                int eqs = eqb, selr = selb;
                const short* cbase = cidx + h * 16;
#pragma unroll
                for (int j = 0; j < 16; ++j) {
                    bool gt = k[j] > vT;
                    bool eq = (k[j] == vT);
                    bool sel = gt || (eq && (eqs < rem));
                    if (sel) atomicAdd(&acc[selr * DD + (int)cbase[j]], 1);
                    selr += sel;
                    eqs  += eq;
                }
            }
        }
        __syncwarp();
    }

    __syncthreads();

    // ---- exact fallback for flagged rows (warp-cooperative, rare) ----
    {
        const int fc = min(*flagCnt, NN);
        for (int f = warp; f < fc; f += NWARPS) {
            const float* row = nbase + (size_t)flagN[f] * DD;
            fallback_select(row, xb, sigma, acc, lane, lt);
        }
    }
    __syncthreads();

    const float inv = 1.0f / (float)NN;
    float* ob = out + (size_t)b * KK * DD;
    for (int i = tid; i < KK * DD; i += THREADS)
        ob[i] = (float)acc[i] * inv;
}

extern "C" void kernel_launch(void* const* d_in, const int* in_sizes, int n_in,
                              void* d_out, int out_size)
{
    const float* x     = nullptr;
    const float* noise = nullptr;
    const float* sigma = nullptr;
    for (int i = 0; i < n_in; ++i) {
        if      (in_sizes[i] == BB * DD)      x     = (const float*)d_in[i];
        else if (in_sizes[i] == BB * NN * DD) noise = (const float*)d_in[i];
        else if (in_sizes[i] == 1)            sigma = (const float*)d_in[i];
    }
    cudaFuncSetAttribute(ptk_kernel, cudaFuncAttributeMaxDynamicSharedMemorySize,
                         SMEM_TOTAL);
    ptk_kernel<<<BB, THREADS, SMEM_TOTAL>>>(x, noise, sigma, (float*)d_out);
}